// round 13
// baseline (speedup 1.0000x reference)
#include <cuda_runtime.h>
#include <cuda_bf16.h>
#include <cstdint>

// ---------------------------------------------------------------------------
// ToFace_Unet_Dwt_locate — R13: R12 with the W1 fragment-array sizing bug
// fixed (16 n-tiles, not 8). HMMA bf16 3-term split; weight B-fragments
// pre-packed fragment-linear in global (L2-resident), no weight smem;
// smem = A/H only (36.9KB) -> 3 CTAs/SM.
// ---------------------------------------------------------------------------

#define H0_0 0.48296291314469025f
#define H0_1 0.836516303737469f
#define H0_2 0.22414386804185735f
#define H0_3 (-0.12940952255092145f)
#define H1_0 0.12940952255092145f
#define H1_1 (-0.22414386804185735f)
#define H1_2 0.836516303737469f
#define H1_3 (-0.48296291314469025f)

#define B_DIM 16
#define C_IN 360
#define HW 4096
#define C_MID 180

// smem word offsets
#define WB1    0          // b1: 128 f32
#define WB2    128        // b2: 256 f32 (pad to 512)
#define WA_HI  512        // A hi [64][52] (ends 3840)
#define WA_LO  3840       // A lo [64][52] (ends 7168)
#define WH_HI  512        // H hi [64][68] (overlays A post-GEMM1)
#define WH_LO  4864       // H lo [64][68] (ends 9216)
#define SMEM_WORDS 9216
#define SMEM_BYTES (SMEM_WORDS * 4)   // 36864

#define A_ST  52
#define H_ST  68

__device__ float g_F[(size_t)B_DIM * C_MID * HW];   // 47.2 MB scratch
// W1 fragments: index = ((s*16 + nt)*2 + hl)*64 + l*2 + j   (6 s x 16 nt)
__device__ uint32_t g_W1f[12288];
// W2 fragments: index = (((q*8 + s)*8 + nt)*2 + hl)*64 + l*2 + j
__device__ uint32_t g_W2f[32768];

// ---- helpers --------------------------------------------------------------
__device__ __forceinline__ uint32_t pack_bf16(__nv_bfloat16 lo, __nv_bfloat16 hi) {
    return ((uint32_t)__bfloat16_as_ushort(hi) << 16) | __bfloat16_as_ushort(lo);
}
__device__ __forceinline__ void split_pair(float v0, float v1,
                                           uint32_t& whi, uint32_t& wlo) {
    __nv_bfloat16 h0 = __float2bfloat16(v0);
    __nv_bfloat16 h1 = __float2bfloat16(v1);
    float r0 = v0 - __bfloat162float(h0);
    float r1 = v1 - __bfloat162float(h1);
    whi = pack_bf16(h0, h1);
    wlo = pack_bf16(__float2bfloat16(r0), __float2bfloat16(r1));
}
__device__ __forceinline__ uint32_t split_word(float v0, float v1, int hl) {
    uint32_t a, b;
    split_pair(v0, v1, a, b);
    return hl ? b : a;
}
__device__ __forceinline__ void mma16816(float* d, const uint32_t* a,
                                         const uint32_t* b) {
    asm volatile(
        "mma.sync.aligned.m16n8k16.row.col.f32.bf16.bf16.f32 "
        "{%0,%1,%2,%3}, {%4,%5,%6,%7}, {%8,%9}, {%0,%1,%2,%3};"
        : "+f"(d[0]), "+f"(d[1]), "+f"(d[2]), "+f"(d[3])
        : "r"(a[0]), "r"(a[1]), "r"(a[2]), "r"(a[3]), "r"(b[0]), "r"(b[1]));
}
__device__ __forceinline__ void ldsm4(uint32_t* r, uint32_t saddr) {
    asm volatile("ldmatrix.sync.aligned.m8n8.x4.shared.b16 {%0,%1,%2,%3}, [%4];"
                 : "=r"(r[0]), "=r"(r[1]), "=r"(r[2]), "=r"(r[3]) : "r"(saddr));
}

// ---------------------------------------------------------------------------
// Kernel 1: DWT (z 0..5) + weight fragment-pack prologue (z == 6).
// Fragment content (b-operand of m16n8k16, matching ldmatrix mapping):
//   reg j of lane l for n-tile nt, k-step s = W[n = nt*8 + (l>>2)]
//                                             [k-pair wd = s*8 + j*4 + (l&3)]
// ---------------------------------------------------------------------------
__global__ void __launch_bounds__(256) dwt_kernel(const float* __restrict__ X,
                                                  const float* __restrict__ w1,
                                                  const float* __restrict__ w2)
{
    if (blockIdx.z == 6) {
        int i = (blockIdx.y * 16 + blockIdx.x) * 256 + threadIdx.x;
        if (i < 12288) {                 // W1 fragments: 6 steps x 16 n-tiles
            int j = i & 1, l = (i >> 1) & 31;
            int rest = i >> 6;           // ((s*16 + nt)*2 + hl)
            int hl = rest & 1, nt = (rest >> 1) & 15, s = rest >> 5;
            int n  = nt * 8 + (l >> 2);
            int wd = s * 8 + j * 4 + (l & 3);
            int k0 = 2 * wd;
            float v0 = (k0     < 90) ? w1[n * 90 + k0]     : 0.f;
            float v1 = (k0 + 1 < 90) ? w1[n * 90 + k0 + 1] : 0.f;
            g_W1f[i] = split_word(v0, v1, hl);
        } else if (i < 12288 + 32768) {  // W2 fragments: 4 q x 8 steps x 8 nt
            int m = i - 12288;
            int j = m & 1, l = (m >> 1) & 31;
            int rest = m >> 6;
            int hl = rest & 1, nt = (rest >> 1) & 7;
            int s = (rest >> 4) & 7, q = rest >> 7;
            int n  = q * 64 + nt * 8 + (l >> 2);
            int wd = s * 8 + j * 4 + (l & 3);
            int k0 = 2 * wd;
            float v0 = w2[n * 128 + k0];
            float v1 = w2[n * 128 + k0 + 1];
            g_W2f[m] = split_word(v0, v1, hl);
        }
        return;
    }

    const int hw = blockIdx.x * 256 + threadIdx.x;
    const int b  = blockIdx.y;
    const int c0 = blockIdx.z * 15;

    const float* Xp = X + (size_t)b * C_IN * HW + hw;

    const int jstart = 2 * c0 - 2;
    float h1v[32];

    int j = jstart;
    int cA = 2 * j - 2, cB = 2 * j - 1;
    float xm2 = (cA >= 0 && cA < C_IN) ? Xp[(size_t)cA * HW] : 0.f;
    float xm1 = (cB >= 0 && cB < C_IN) ? Xp[(size_t)cB * HW] : 0.f;
#pragma unroll
    for (int t = 0; t < 32; t++) {
        int c2j = 2 * j, c2j1 = 2 * j + 1;
        float x0 = (c2j  >= 0 && c2j  < C_IN) ? Xp[(size_t)c2j  * HW] : 0.f;
        float x1 = (c2j1 >= 0 && c2j1 < C_IN) ? Xp[(size_t)c2j1 * HW] : 0.f;
        float h = 0.f;
        if (j >= 0 && j < 180)
            h = H1_0 * xm2 + H1_1 * xm1 + H1_2 * x0 + H1_3 * x1;
        h1v[t] = h;
        xm2 = x0; xm1 = x1; j++;
    }

    float* Fp = g_F + (size_t)b * C_MID * HW + hw;
#pragma unroll
    for (int u = 0; u < 15; u++) {
        int c2 = c0 + u;
        float a = h1v[2 * u], bb = h1v[2 * u + 1], cc = h1v[2 * u + 2], dd = h1v[2 * u + 3];
        float lo = H0_0 * a + H0_1 * bb + H0_2 * cc + H0_3 * dd;
        float hi = H1_0 * a + H1_1 * bb + H1_2 * cc + H1_3 * dd;
        Fp[(size_t)c2 * HW]        = lo;
        Fp[(size_t)(90 + c2) * HW] = hi;
    }
}

// ---------------------------------------------------------------------------
// Kernel 2: HMMA conv+MLP. 1024 blocks x 256 threads, 64 chunks/block,
// 3 CTAs/SM. B-operands loaded from global fragment arrays (no weight smem).
// ---------------------------------------------------------------------------
__global__ void __launch_bounds__(256, 3) mlp_kernel(
    const float* __restrict__ cw, const float* __restrict__ cbp,
    const float* __restrict__ b1, const float* __restrict__ b2,
    float* __restrict__ out)
{
    extern __shared__ uint32_t sw[];
    float* b1s = (float*)(sw + WB1);
    float* b2s = (float*)(sw + WB2);
    const uint32_t swb = (uint32_t)__cvta_generic_to_shared(sw);

    const int tid = threadIdx.x;
    const int n0  = blockIdx.x * 64;
    const int w   = tid >> 5, l = tid & 31;
    const int wm  = w & 1, wn = w >> 1;      // 2 m-warps x 4 n-warps
    const int g   = l >> 2, kp = l & 3;

    const int a_lrow = l & 15;
    const int a_lcol = (l >> 4) * 4;

    // ---- biases ----
    if (tid < 128) b1s[tid] = b1[tid];
    b2s[tid] = b2[tid];

    // ---- conv: direct-LDG from g_F -> A splits in smem ----
    {
        float c0w[7], c1w[7];
#pragma unroll
        for (int i = 0; i < 7; i++) { c0w[i] = cw[i]; c1w[i] = cw[7 + i]; }
        const float cb = cbp[0];
        const int mloc = tid >> 3, q8 = tid & 7;

#pragma unroll
        for (int fh = 0; fh < 2; fh++) {
            const int mrow = fh * 32 + mloc;
            const float* r0 = g_F + (size_t)(n0 + mrow) * 180;
            const float* r1 = r0 + 90;
            float a0[18], a1[18];
#pragma unroll
            for (int t = 0; t < 18; t++) {
                int idx = q8 * 12 - 3 + t;
                bool ok = (idx >= 0 && idx < 90);
                a0[t] = ok ? __ldg(r0 + idx) : 0.f;
                a1[t] = ok ? __ldg(r1 + idx) : 0.f;
            }
            uint32_t* Ah = sw + WA_HI + mrow * A_ST;
            uint32_t* Al = sw + WA_LO + mrow * A_ST;
#pragma unroll
            for (int pl = 0; pl < 6; pl++) {
                int p = q8 * 6 + pl;
                float v0 = 0.f, v1 = 0.f;
                if (2 * p < 90) {
                    float s0 = cb, s1 = cb;
#pragma unroll
                    for (int kw = 0; kw < 7; kw++) {
                        s0 += c0w[kw] * a0[2 * pl + kw]     + c1w[kw] * a1[2 * pl + kw];
                        s1 += c0w[kw] * a0[2 * pl + 1 + kw] + c1w[kw] * a1[2 * pl + 1 + kw];
                    }
                    v0 = fmaxf(s0, 0.f);
                    v1 = fmaxf(s1, 0.f);
                }
                uint32_t whi, wlo;
                split_pair(v0, v1, whi, wlo);
                Ah[p] = whi;
                Al[p] = wlo;
            }
        }
    }
    __syncthreads();

    // ---- GEMM1: [64m x 128n], K=96 (6 steps), 3-term, term-major ----
    float acc1[2][4][4];
#pragma unroll
    for (int mi = 0; mi < 2; mi++)
#pragma unroll
        for (int t = 0; t < 4; t++)
#pragma unroll
            for (int e = 0; e < 4; e++) acc1[mi][t][e] = 0.f;

    {
        uint32_t aHi[2], aLo[2];
#pragma unroll
        for (int mi = 0; mi < 2; mi++) {
            int row = (wm * 2 + mi) * 16 + a_lrow;
            aHi[mi] = swb + 4 * (WA_HI + row * A_ST + a_lcol);
            aLo[mi] = swb + 4 * (WA_LO + row * A_ST + a_lcol);
        }
        const uint2* W1f = (const uint2*)g_W1f;   // [((s*16+nt)*2+hl)*32 + l]

#pragma unroll
        for (int s = 0; s < 6; s++) {
            uint32_t ah[2][4], al[2][4];
            const uint32_t so = s * 32;
            ldsm4(ah[0], aHi[0] + so); ldsm4(ah[1], aHi[1] + so);
            ldsm4(al[0], aLo[0] + so); ldsm4(al[1], aLo[1] + so);
            uint2 bh[4], bl[4];
#pragma unroll
            for (int t = 0; t < 4; t++) {
                int base = ((s * 16 + wn * 4 + t) * 2) * 32 + l;
                bh[t] = __ldg(W1f + base);
                bl[t] = __ldg(W1f + base + 32);
            }
#pragma unroll
            for (int t = 0; t < 4; t++)
#pragma unroll
                for (int mi = 0; mi < 2; mi++)
                    mma16816(acc1[mi][t], ah[mi], (const uint32_t*)&bh[t]);
#pragma unroll
            for (int t = 0; t < 4; t++)
#pragma unroll
                for (int mi = 0; mi < 2; mi++)
                    mma16816(acc1[mi][t], ah[mi], (const uint32_t*)&bl[t]);
#pragma unroll
            for (int t = 0; t < 4; t++)
#pragma unroll
                for (int mi = 0; mi < 2; mi++)
                    mma16816(acc1[mi][t], al[mi], (const uint32_t*)&bh[t]);
        }
    }
    __syncthreads();       // all A reads done before H overwrites the region

    // ---- epilogue 1: relu(+b1) -> H splits (overlays A region) ----
#pragma unroll
    for (int mi = 0; mi < 2; mi++) {
        int r1 = (wm * 2 + mi) * 16 + g, r2 = r1 + 8;
#pragma unroll
        for (int t = 0; t < 4; t++) {
            int tile = wn * 4 + t;
            int c = tile * 8 + kp * 2;
            float bb0 = b1s[c], bb1 = b1s[c + 1];
            int wc = tile * 4 + kp;
            float v0 = fmaxf(acc1[mi][t][0] + bb0, 0.f);
            float v1 = fmaxf(acc1[mi][t][1] + bb1, 0.f);
            uint32_t whi, wlo;
            split_pair(v0, v1, whi, wlo);
            sw[WH_HI + r1 * H_ST + wc] = whi;
            sw[WH_LO + r1 * H_ST + wc] = wlo;
            float v2 = fmaxf(acc1[mi][t][2] + bb0, 0.f);
            float v3 = fmaxf(acc1[mi][t][3] + bb1, 0.f);
            split_pair(v2, v3, whi, wlo);
            sw[WH_HI + r2 * H_ST + wc] = whi;
            sw[WH_LO + r2 * H_ST + wc] = wlo;
        }
    }
    __syncthreads();       // H visible

    // ---- GEMM2: 4 N-quarters of 64, K=128 (8 steps), no inner barriers ----
    uint32_t hHi[2], hLo[2];
#pragma unroll
    for (int mi = 0; mi < 2; mi++) {
        int row = (wm * 2 + mi) * 16 + a_lrow;
        hHi[mi] = swb + 4 * (WH_HI + row * H_ST + a_lcol);
        hLo[mi] = swb + 4 * (WH_LO + row * H_ST + a_lcol);
    }
    const uint2* W2f = (const uint2*)g_W2f;   // [(((q*8+s)*8+nt)*2+hl)*32 + l]

#pragma unroll
    for (int q = 0; q < 4; q++) {
        float acc2[2][2][4];
#pragma unroll
        for (int mi = 0; mi < 2; mi++)
#pragma unroll
            for (int t = 0; t < 2; t++)
#pragma unroll
                for (int e = 0; e < 4; e++) acc2[mi][t][e] = 0.f;

#pragma unroll
        for (int s = 0; s < 8; s++) {
            uint32_t ah[2][4], al[2][4];
            const uint32_t so = s * 32;
            ldsm4(ah[0], hHi[0] + so); ldsm4(ah[1], hHi[1] + so);
            ldsm4(al[0], hLo[0] + so); ldsm4(al[1], hLo[1] + so);
            uint2 bh[2], bl[2];
#pragma unroll
            for (int t = 0; t < 2; t++) {
                int base = (((q * 8 + s) * 8 + wn * 2 + t) * 2) * 32 + l;
                bh[t] = __ldg(W2f + base);
                bl[t] = __ldg(W2f + base + 32);
            }
#pragma unroll
            for (int t = 0; t < 2; t++)
#pragma unroll
                for (int mi = 0; mi < 2; mi++)
                    mma16816(acc2[mi][t], ah[mi], (const uint32_t*)&bh[t]);
#pragma unroll
            for (int t = 0; t < 2; t++)
#pragma unroll
                for (int mi = 0; mi < 2; mi++)
                    mma16816(acc2[mi][t], ah[mi], (const uint32_t*)&bl[t]);
#pragma unroll
            for (int t = 0; t < 2; t++)
#pragma unroll
                for (int mi = 0; mi < 2; mi++)
                    mma16816(acc2[mi][t], al[mi], (const uint32_t*)&bh[t]);
        }

        // epilogue: +b2 -> out
#pragma unroll
        for (int mi = 0; mi < 2; mi++) {
            int r1 = (wm * 2 + mi) * 16 + g, r2 = r1 + 8;
#pragma unroll
            for (int t = 0; t < 2; t++) {
                int c = q * 64 + (wn * 2 + t) * 8 + kp * 2;
                float bb0 = b2s[c], bb1 = b2s[c + 1];
                float2 v01 = make_float2(acc2[mi][t][0] + bb0, acc2[mi][t][1] + bb1);
                float2 v23 = make_float2(acc2[mi][t][2] + bb0, acc2[mi][t][3] + bb1);
                *(float2*)(out + (size_t)(n0 + r1) * 256 + c) = v01;
                *(float2*)(out + (size_t)(n0 + r2) * 256 + c) = v23;
            }
        }
    }
}

// ---------------------------------------------------------------------------
extern "C" void kernel_launch(void* const* d_in, const int* in_sizes, int n_in,
                              void* d_out, int out_size)
{
    const float* x      = (const float*)d_in[0];
    const float* conv_w = (const float*)d_in[1];
    const float* conv_b = (const float*)d_in[2];
    const float* w1     = (const float*)d_in[3];
    const float* b1     = (const float*)d_in[4];
    const float* w2     = (const float*)d_in[5];
    const float* b2     = (const float*)d_in[6];
    float* out = (float*)d_out;

    (void)in_sizes; (void)n_in; (void)out_size;

    // Stage 1: double DWT -> g_F, plus weight fragment pack in z-slice 6
    dim3 g1(HW / 256, B_DIM, 7);
    dwt_kernel<<<g1, 256>>>(x, w1, w2);

    // Stage 2: conv + HMMA MLP (3 CTAs/SM)
    cudaFuncSetAttribute(mlp_kernel,
                         cudaFuncAttributeMaxDynamicSharedMemorySize, SMEM_BYTES);
    mlp_kernel<<<1024, 256, SMEM_BYTES>>>(conv_w, conv_b, b1, b2, out);
}

// round 14
// speedup vs baseline: 1.7935x; 1.7935x over previous
#include <cuda_runtime.h>
#include <cuda_bf16.h>
#include <cstdint>

// ---------------------------------------------------------------------------
// ToFace_Unet_Dwt_locate — R14: R11 (HMMA bf16 3-term split, smem weights,
// M=64 tiles, 2 CTAs/SM) made PERSISTENT: 304 CTAs work-steal 1024 tiles via
// an atomic counter (reset per launch) — removes the 0.54-wave tail (~13%).
// ---------------------------------------------------------------------------

#define H0_0 0.48296291314469025f
#define H0_1 0.836516303737469f
#define H0_2 0.22414386804185735f
#define H0_3 (-0.12940952255092145f)
#define H1_0 0.12940952255092145f
#define H1_1 (-0.22414386804185735f)
#define H1_2 0.836516303737469f
#define H1_3 (-0.48296291314469025f)

#define B_DIM 16
#define C_IN 360
#define HW 4096
#define C_MID 180

// smem word offsets (same layout as R11)
#define WB1    0          // b1: 128 f32
#define WB2    128        // b2: 256 f32 (384..512 pad; word 448 = tile bcast)
#define WA_HI  512        // A hi [64][52] (ends 3840)
#define WA_LO  3840       // A lo [64][52] (ends 7168)
#define WH_HI  512        // H hi [64][68] (overlays A post-GEMM1)
#define WH_LO  4864       // H lo [64][68] (ends 9216)
#define WW1_HI 9216       // W1 hi [128][52] (ends 15872)
#define WW1_LO 15872      // W1 lo [128][52] (ends 22528)
#define QB0    9216       // W2 quarter buf0 (aliases W1 after GEMM1)
#define QB1    17920      // W2 quarter buf1 (ends 26624)
#define QLO    4352
#define SMEM_WORDS 26624
#define SMEM_BYTES (SMEM_WORDS * 4)   // 106496

#define A_ST  52
#define W1_ST 52
#define W2_ST 68
#define H_ST  68

#define NTILES 1024u

__device__ float g_F[(size_t)B_DIM * C_MID * HW];   // 47.2 MB scratch
__device__ uint32_t g_W1s[12288];                   // [hl][128][48 words]
__device__ uint32_t g_W2s[32768];                   // [q][hl][64][64 words]
__device__ unsigned int g_ctr;

// ---- helpers --------------------------------------------------------------
__device__ __forceinline__ uint32_t pack_bf16(__nv_bfloat16 lo, __nv_bfloat16 hi) {
    return ((uint32_t)__bfloat16_as_ushort(hi) << 16) | __bfloat16_as_ushort(lo);
}
__device__ __forceinline__ void split_pair(float v0, float v1,
                                           uint32_t& whi, uint32_t& wlo) {
    __nv_bfloat16 h0 = __float2bfloat16(v0);
    __nv_bfloat16 h1 = __float2bfloat16(v1);
    float r0 = v0 - __bfloat162float(h0);
    float r1 = v1 - __bfloat162float(h1);
    whi = pack_bf16(h0, h1);
    wlo = pack_bf16(__float2bfloat16(r0), __float2bfloat16(r1));
}
__device__ __forceinline__ uint32_t split_word(float v0, float v1, int hl) {
    uint32_t a, b;
    split_pair(v0, v1, a, b);
    return hl ? b : a;
}
__device__ __forceinline__ void mma16816(float* d, const uint32_t* a,
                                         const uint32_t* b) {
    asm volatile(
        "mma.sync.aligned.m16n8k16.row.col.f32.bf16.bf16.f32 "
        "{%0,%1,%2,%3}, {%4,%5,%6,%7}, {%8,%9}, {%0,%1,%2,%3};"
        : "+f"(d[0]), "+f"(d[1]), "+f"(d[2]), "+f"(d[3])
        : "r"(a[0]), "r"(a[1]), "r"(a[2]), "r"(a[3]), "r"(b[0]), "r"(b[1]));
}
__device__ __forceinline__ void ldsm4(uint32_t* r, uint32_t saddr) {
    asm volatile("ldmatrix.sync.aligned.m8n8.x4.shared.b16 {%0,%1,%2,%3}, [%4];"
                 : "=r"(r[0]), "=r"(r[1]), "=r"(r[2]), "=r"(r[3]) : "r"(saddr));
}
__device__ __forceinline__ void cp16(uint32_t dst_sw, const void* src) {
    asm volatile("cp.async.cg.shared.global [%0], [%1], 16;"
                 :: "r"(dst_sw), "l"(src));
}
#define CP_COMMIT() asm volatile("cp.async.commit_group;" ::: "memory")
#define CP_WAIT(N)  asm volatile("cp.async.wait_group %0;" :: "n"(N) : "memory")

// ---------------------------------------------------------------------------
__global__ void reset_ctr_kernel() { g_ctr = 0u; }

// ---------------------------------------------------------------------------
// Kernel 1: DWT (z 0..5) + weight split prologue (z == 6). grid (16,16,7)x256.
// ---------------------------------------------------------------------------
__global__ void __launch_bounds__(256) dwt_kernel(const float* __restrict__ X,
                                                  const float* __restrict__ w1,
                                                  const float* __restrict__ w2)
{
    if (blockIdx.z == 6) {
        int i = (blockIdx.y * 16 + blockIdx.x) * 256 + threadIdx.x;
        if (i < 12288) {                 // W1 words: [hl][n 128][wd 48]
            int hl = i / 6144, rr = i % 6144;
            int n = rr / 48, wd = rr % 48;
            int k0 = 2 * wd;
            float v0 = (k0     < 90) ? w1[n * 90 + k0]     : 0.f;
            float v1 = (k0 + 1 < 90) ? w1[n * 90 + k0 + 1] : 0.f;
            g_W1s[i] = split_word(v0, v1, hl);
        } else if (i < 12288 + 32768) {  // W2 words: [q][hl][n 64][wd 64]
            int j = i - 12288;
            int q  = j >> 13, r1 = j & 8191;
            int hl = r1 >> 12, r2 = r1 & 4095;
            int n  = r2 >> 6,  wd = r2 & 63;
            int ng = q * 64 + n, k0 = 2 * wd;
            float v0 = w2[ng * 128 + k0];
            float v1 = w2[ng * 128 + k0 + 1];
            g_W2s[j] = split_word(v0, v1, hl);
        }
        return;
    }

    const int hw = blockIdx.x * 256 + threadIdx.x;
    const int b  = blockIdx.y;
    const int c0 = blockIdx.z * 15;

    const float* Xp = X + (size_t)b * C_IN * HW + hw;

    const int jstart = 2 * c0 - 2;
    float h1v[32];

    int j = jstart;
    int cA = 2 * j - 2, cB = 2 * j - 1;
    float xm2 = (cA >= 0 && cA < C_IN) ? Xp[(size_t)cA * HW] : 0.f;
    float xm1 = (cB >= 0 && cB < C_IN) ? Xp[(size_t)cB * HW] : 0.f;
#pragma unroll
    for (int t = 0; t < 32; t++) {
        int c2j = 2 * j, c2j1 = 2 * j + 1;
        float x0 = (c2j  >= 0 && c2j  < C_IN) ? Xp[(size_t)c2j  * HW] : 0.f;
        float x1 = (c2j1 >= 0 && c2j1 < C_IN) ? Xp[(size_t)c2j1 * HW] : 0.f;
        float h = 0.f;
        if (j >= 0 && j < 180)
            h = H1_0 * xm2 + H1_1 * xm1 + H1_2 * x0 + H1_3 * x1;
        h1v[t] = h;
        xm2 = x0; xm1 = x1; j++;
    }

    float* Fp = g_F + (size_t)b * C_MID * HW + hw;
#pragma unroll
    for (int u = 0; u < 15; u++) {
        int c2 = c0 + u;
        float a = h1v[2 * u], bb = h1v[2 * u + 1], cc = h1v[2 * u + 2], dd = h1v[2 * u + 3];
        float lo = H0_0 * a + H0_1 * bb + H0_2 * cc + H0_3 * dd;
        float hi = H1_0 * a + H1_1 * bb + H1_2 * cc + H1_3 * dd;
        Fp[(size_t)c2 * HW]        = lo;
        Fp[(size_t)(90 + c2) * HW] = hi;
    }
}

// ---------------------------------------------------------------------------
// Kernel 2: persistent HMMA conv+MLP. 304 CTAs x 256 threads, work-steal
// 1024 tiles of 64 chunks. 2 CTAs/SM.
// ---------------------------------------------------------------------------
__global__ void __launch_bounds__(256, 2) mlp_kernel(
    const float* __restrict__ cw, const float* __restrict__ cbp,
    const float* __restrict__ b1, const float* __restrict__ b2,
    float* __restrict__ out)
{
    extern __shared__ uint32_t sw[];
    float* b1s = (float*)(sw + WB1);
    float* b2s = (float*)(sw + WB2);
    const uint32_t swb = (uint32_t)__cvta_generic_to_shared(sw);

    const int tid = threadIdx.x;
    const int w   = tid >> 5, l = tid & 31;
    const int wm  = w & 1, wn = w >> 1;      // 2 m-warps x 4 n-warps
    const int g   = l >> 2, kp = l & 3;

    const int a_lrow = l & 15;
    const int a_lcol = (l >> 4) * 4;
    const int b_sel  = l >> 3, b_r8 = l & 7;
    const int b_tof  = (b_sel >> 1);
    const int b_col  = (b_sel & 1) * 4;

    // conv weights + biases once
    float c0w[7], c1w[7];
#pragma unroll
    for (int i = 0; i < 7; i++) { c0w[i] = __ldg(cw + i); c1w[i] = __ldg(cw + 7 + i); }
    const float cb = __ldg(cbp);
    if (tid < 128) b1s[tid] = b1[tid];
    b2s[tid] = b2[tid];

    for (;;) {
        if (tid == 0) sw[448] = atomicAdd(&g_ctr, 1u);
        __syncthreads();                  // tile bcast + prev-tile smem quiesce
        const uint32_t tile = sw[448];
        if (tile >= NTILES) break;
        const int n0 = (int)tile * 64;

        // ---- W1 cp.async (lands during conv) ----
#pragma unroll
        for (int c = 0; c < 12; c++) {
            int i = tid + c * 256;                   // 3072 ops
            int hl = i / 1536, rr = i % 1536;
            int n = rr / 12, jq = rr % 12;
            uint32_t dst = swb + 4 * ((hl ? WW1_LO : WW1_HI) + n * W1_ST + jq * 4);
            cp16(dst, g_W1s + hl * 6144 + n * 48 + jq * 4);
        }
        CP_COMMIT();

        // ---- conv: direct-LDG from g_F -> A splits ----
        {
            const int mloc = tid >> 3, q8 = tid & 7;
#pragma unroll
            for (int fh = 0; fh < 2; fh++) {
                const int mrow = fh * 32 + mloc;
                const float* r0 = g_F + (size_t)(n0 + mrow) * 180;
                const float* r1 = r0 + 90;
                float a0[18], a1[18];
#pragma unroll
                for (int t = 0; t < 18; t++) {
                    int idx = q8 * 12 - 3 + t;
                    bool ok = (idx >= 0 && idx < 90);
                    a0[t] = ok ? __ldg(r0 + idx) : 0.f;
                    a1[t] = ok ? __ldg(r1 + idx) : 0.f;
                }
                uint32_t* Ah = sw + WA_HI + mrow * A_ST;
                uint32_t* Al = sw + WA_LO + mrow * A_ST;
#pragma unroll
                for (int pl = 0; pl < 6; pl++) {
                    int p = q8 * 6 + pl;
                    float v0 = 0.f, v1 = 0.f;
                    if (2 * p < 90) {
                        float s0 = cb, s1 = cb;
#pragma unroll
                        for (int kw = 0; kw < 7; kw++) {
                            s0 += c0w[kw] * a0[2 * pl + kw]     + c1w[kw] * a1[2 * pl + kw];
                            s1 += c0w[kw] * a0[2 * pl + 1 + kw] + c1w[kw] * a1[2 * pl + 1 + kw];
                        }
                        v0 = fmaxf(s0, 0.f);
                        v1 = fmaxf(s1, 0.f);
                    }
                    uint32_t whi, wlo;
                    split_pair(v0, v1, whi, wlo);
                    Ah[p] = whi;
                    Al[p] = wlo;
                }
            }
        }
        CP_WAIT(0);            // W1 landed
        __syncthreads();

        // ---- GEMM1: [64m x 128n], K=96 (6 steps), 3-term, term-major ----
        float acc1[2][4][4];
#pragma unroll
        for (int mi = 0; mi < 2; mi++)
#pragma unroll
            for (int t = 0; t < 4; t++)
#pragma unroll
                for (int e = 0; e < 4; e++) acc1[mi][t][e] = 0.f;

        {
            uint32_t aHi[2], aLo[2], bHi[2], bLo[2];
#pragma unroll
            for (int mi = 0; mi < 2; mi++) {
                int row = (wm * 2 + mi) * 16 + a_lrow;
                aHi[mi] = swb + 4 * (WA_HI + row * A_ST + a_lcol);
                aLo[mi] = swb + 4 * (WA_LO + row * A_ST + a_lcol);
            }
#pragma unroll
            for (int tp = 0; tp < 2; tp++) {
                int n = (wn * 4 + 2 * tp + b_tof) * 8 + b_r8;
                bHi[tp] = swb + 4 * (WW1_HI + n * W1_ST + b_col);
                bLo[tp] = swb + 4 * (WW1_LO + n * W1_ST + b_col);
            }
#pragma unroll
            for (int s = 0; s < 6; s++) {
                uint32_t ah[2][4], al[2][4], bh[2][4], bl[2][4];
                const uint32_t so = s * 32;
                ldsm4(ah[0], aHi[0] + so); ldsm4(ah[1], aHi[1] + so);
                ldsm4(al[0], aLo[0] + so); ldsm4(al[1], aLo[1] + so);
                ldsm4(bh[0], bHi[0] + so); ldsm4(bh[1], bHi[1] + so);
                ldsm4(bl[0], bLo[0] + so); ldsm4(bl[1], bLo[1] + so);
#pragma unroll
                for (int t = 0; t < 4; t++)
#pragma unroll
                    for (int mi = 0; mi < 2; mi++)
                        mma16816(acc1[mi][t], ah[mi], &bh[t >> 1][(t & 1) * 2]);
#pragma unroll
                for (int t = 0; t < 4; t++)
#pragma unroll
                    for (int mi = 0; mi < 2; mi++)
                        mma16816(acc1[mi][t], ah[mi], &bl[t >> 1][(t & 1) * 2]);
#pragma unroll
                for (int t = 0; t < 4; t++)
#pragma unroll
                    for (int mi = 0; mi < 2; mi++)
                        mma16816(acc1[mi][t], al[mi], &bh[t >> 1][(t & 1) * 2]);
            }
        }
        __syncthreads();       // W1 + A reads done; regions may be overwritten

        // ---- prefetch W2 quarters 0,1 into qbufs (alias dead W1 region) ----
#pragma unroll
        for (int qq = 0; qq < 2; qq++) {
#pragma unroll
            for (int c = 0; c < 8; c++) {
                int i = tid + c * 256;               // 2048 ops per quarter
                int hl = i >> 10, rr = i & 1023;
                int n = rr >> 4, jq = rr & 15;
                uint32_t qb = qq ? QB1 : QB0;
                uint32_t dst = swb + 4 * (qb + (hl ? QLO : 0) + n * W2_ST + jq * 4);
                cp16(dst, g_W2s + qq * 8192 + hl * 4096 + n * 64 + jq * 4);
            }
            CP_COMMIT();
        }

        // ---- epilogue 1: relu(+b1) -> H splits (overlays A region) ----
#pragma unroll
        for (int mi = 0; mi < 2; mi++) {
            int r1 = (wm * 2 + mi) * 16 + g, r2 = r1 + 8;
#pragma unroll
            for (int t = 0; t < 4; t++) {
                int tile2 = wn * 4 + t;
                int c = tile2 * 8 + kp * 2;
                float bb0 = b1s[c], bb1 = b1s[c + 1];
                int wc = tile2 * 4 + kp;
                float v0 = fmaxf(acc1[mi][t][0] + bb0, 0.f);
                float v1 = fmaxf(acc1[mi][t][1] + bb1, 0.f);
                uint32_t whi, wlo;
                split_pair(v0, v1, whi, wlo);
                sw[WH_HI + r1 * H_ST + wc] = whi;
                sw[WH_LO + r1 * H_ST + wc] = wlo;
                float v2 = fmaxf(acc1[mi][t][2] + bb0, 0.f);
                float v3 = fmaxf(acc1[mi][t][3] + bb1, 0.f);
                split_pair(v2, v3, whi, wlo);
                sw[WH_HI + r2 * H_ST + wc] = whi;
                sw[WH_LO + r2 * H_ST + wc] = wlo;
            }
        }
        CP_WAIT(1);            // q0 landed (q1 may fly)
        __syncthreads();       // H + qbuf0 visible

        // ---- GEMM2: 4 N-quarters of 64, K=128, double-buffered tiles ----
        uint32_t hHi[2], hLo[2];
#pragma unroll
        for (int mi = 0; mi < 2; mi++) {
            int row = (wm * 2 + mi) * 16 + a_lrow;
            hHi[mi] = swb + 4 * (WH_HI + row * H_ST + a_lcol);
            hLo[mi] = swb + 4 * (WH_LO + row * H_ST + a_lcol);
        }
        const int nloc = (wn * 2 + b_tof) * 8 + b_r8;   // 0..63 within quarter

#pragma unroll
        for (int q = 0; q < 4; q++) {
            const uint32_t qb = (q & 1) ? QB1 : QB0;
            const uint32_t bHi = swb + 4 * (qb + nloc * W2_ST + b_col);
            const uint32_t bLo = bHi + 4 * QLO;

            float acc2[2][2][4];
#pragma unroll
            for (int mi = 0; mi < 2; mi++)
#pragma unroll
                for (int t = 0; t < 2; t++)
#pragma unroll
                    for (int e = 0; e < 4; e++) acc2[mi][t][e] = 0.f;

#pragma unroll
            for (int s = 0; s < 8; s++) {
                uint32_t ah[2][4], al[2][4], bh[4], bl[4];
                const uint32_t so = s * 32;
                ldsm4(ah[0], hHi[0] + so); ldsm4(ah[1], hHi[1] + so);
                ldsm4(al[0], hLo[0] + so); ldsm4(al[1], hLo[1] + so);
                ldsm4(bh, bHi + so);       ldsm4(bl, bLo + so);
#pragma unroll
                for (int t = 0; t < 2; t++)
#pragma unroll
                    for (int mi = 0; mi < 2; mi++)
                        mma16816(acc2[mi][t], ah[mi], &bh[t * 2]);
#pragma unroll
                for (int t = 0; t < 2; t++)
#pragma unroll
                    for (int mi = 0; mi < 2; mi++)
                        mma16816(acc2[mi][t], ah[mi], &bl[t * 2]);
#pragma unroll
                for (int t = 0; t < 2; t++)
#pragma unroll
                    for (int mi = 0; mi < 2; mi++)
                        mma16816(acc2[mi][t], al[mi], &bh[t * 2]);
            }

            // epilogue: +b2 -> out
#pragma unroll
            for (int mi = 0; mi < 2; mi++) {
                int r1 = (wm * 2 + mi) * 16 + g, r2 = r1 + 8;
#pragma unroll
                for (int t = 0; t < 2; t++) {
                    int c = q * 64 + (wn * 2 + t) * 8 + kp * 2;
                    float bb0 = b2s[c], bb1 = b2s[c + 1];
                    float2 v01 = make_float2(acc2[mi][t][0] + bb0, acc2[mi][t][1] + bb1);
                    float2 v23 = make_float2(acc2[mi][t][2] + bb0, acc2[mi][t][3] + bb1);
                    *(float2*)(out + (size_t)(n0 + r1) * 256 + c) = v01;
                    *(float2*)(out + (size_t)(n0 + r2) * 256 + c) = v23;
                }
            }

            // pipeline control
            if (q < 2) {
                __syncthreads();                    // all reads of this qb done
#pragma unroll
                for (int c = 0; c < 8; c++) {       // prefetch quarter q+2
                    int i = tid + c * 256;
                    int hl = i >> 10, rr = i & 1023;
                    int n = rr >> 4, jq = rr & 15;
                    uint32_t dst = swb + 4 * (qb + (hl ? QLO : 0) + n * W2_ST + jq * 4);
                    cp16(dst, g_W2s + (q + 2) * 8192 + hl * 4096 + n * 64 + jq * 4);
                }
                CP_COMMIT();
                CP_WAIT(1);
                __syncthreads();
            } else if (q == 2) {
                CP_WAIT(0);
                __syncthreads();
            }
        }
    }
}

// ---------------------------------------------------------------------------
extern "C" void kernel_launch(void* const* d_in, const int* in_sizes, int n_in,
                              void* d_out, int out_size)
{
    const float* x      = (const float*)d_in[0];
    const float* conv_w = (const float*)d_in[1];
    const float* conv_b = (const float*)d_in[2];
    const float* w1     = (const float*)d_in[3];
    const float* b1     = (const float*)d_in[4];
    const float* w2     = (const float*)d_in[5];
    const float* b2     = (const float*)d_in[6];
    float* out = (float*)d_out;

    (void)in_sizes; (void)n_in; (void)out_size;

    // reset the work-steal counter (persistent-kernel determinism per launch)
    reset_ctr_kernel<<<1, 1>>>();

    // Stage 1: double DWT -> g_F, plus weight split prologue in z-slice 6
    dim3 g1(HW / 256, B_DIM, 7);
    dwt_kernel<<<g1, 256>>>(x, w1, w2);

    // Stage 2: persistent conv + HMMA MLP (2 CTAs/SM, 152 SMs)
    cudaFuncSetAttribute(mlp_kernel,
                         cudaFuncAttributeMaxDynamicSharedMemorySize, SMEM_BYTES);
    mlp_kernel<<<304, 256, SMEM_BYTES>>>(conv_w, conv_b, b1, b2, out);
}

// round 15
// speedup vs baseline: 1.9714x; 1.0992x over previous
#include <cuda_runtime.h>
#include <cuda_bf16.h>
#include <cstdint>

// ---------------------------------------------------------------------------
// ToFace_Unet_Dwt_locate — R15: HMMA bf16 3-term split, shrunk to 71.7KB smem
// and <=84 regs so 3 CTAs/SM co-reside (24 warps/SM): W1 staged in 2 N-halves
// through one W-buffer (reused for W2 quarters); GEMM1 in 2 N-half passes
// into one 32-reg accumulator.
// ---------------------------------------------------------------------------

#define H0_0 0.48296291314469025f
#define H0_1 0.836516303737469f
#define H0_2 0.22414386804185735f
#define H0_3 (-0.12940952255092145f)
#define H1_0 0.12940952255092145f
#define H1_1 (-0.22414386804185735f)
#define H1_2 0.836516303737469f
#define H1_3 (-0.48296291314469025f)

#define B_DIM 16
#define C_IN 360
#define HW 4096
#define C_MID 180

// smem word offsets
#define WB1    0          // b1: 128 f32
#define WB2    128        // b2: 256 f32 (pad to 512)
#define WA_HI  512        // A hi [64][52] (ends 3840)
#define WA_LO  3840       // A lo [64][52] (ends 7168)
#define WH_HI  512        // H hi [64][68] (overlays A post-GEMM1)
#define WH_LO  4864       // H lo [64][68] (ends 9216)
#define WBUF   9216       // W buffer: W1-half [hl 3328] or W2-quarter [hl 4352]
#define W1LO   3328       // lo offset within WBUF for W1 halves
#define QLO    4352       // lo offset within WBUF for W2 quarters
#define SMEM_WORDS 17920  // 9216 + 8704
#define SMEM_BYTES (SMEM_WORDS * 4)   // 71680

#define A_ST  52
#define W1_ST 52
#define W2_ST 68
#define H_ST  68

__device__ float g_F[(size_t)B_DIM * C_MID * HW];   // 47.2 MB scratch
__device__ uint32_t g_W1s[12288];                   // [hl][128 n][48 wd]
__device__ uint32_t g_W2s[32768];                   // [q][hl][64 n][64 wd]

// ---- helpers --------------------------------------------------------------
__device__ __forceinline__ uint32_t pack_bf16(__nv_bfloat16 lo, __nv_bfloat16 hi) {
    return ((uint32_t)__bfloat16_as_ushort(hi) << 16) | __bfloat16_as_ushort(lo);
}
__device__ __forceinline__ void split_pair(float v0, float v1,
                                           uint32_t& whi, uint32_t& wlo) {
    __nv_bfloat16 h0 = __float2bfloat16(v0);
    __nv_bfloat16 h1 = __float2bfloat16(v1);
    float r0 = v0 - __bfloat162float(h0);
    float r1 = v1 - __bfloat162float(h1);
    whi = pack_bf16(h0, h1);
    wlo = pack_bf16(__float2bfloat16(r0), __float2bfloat16(r1));
}
__device__ __forceinline__ uint32_t split_word(float v0, float v1, int hl) {
    uint32_t a, b;
    split_pair(v0, v1, a, b);
    return hl ? b : a;
}
__device__ __forceinline__ void mma16816(float* d, const uint32_t* a,
                                         const uint32_t* b) {
    asm volatile(
        "mma.sync.aligned.m16n8k16.row.col.f32.bf16.bf16.f32 "
        "{%0,%1,%2,%3}, {%4,%5,%6,%7}, {%8,%9}, {%0,%1,%2,%3};"
        : "+f"(d[0]), "+f"(d[1]), "+f"(d[2]), "+f"(d[3])
        : "r"(a[0]), "r"(a[1]), "r"(a[2]), "r"(a[3]), "r"(b[0]), "r"(b[1]));
}
__device__ __forceinline__ void ldsm4(uint32_t* r, uint32_t saddr) {
    asm volatile("ldmatrix.sync.aligned.m8n8.x4.shared.b16 {%0,%1,%2,%3}, [%4];"
                 : "=r"(r[0]), "=r"(r[1]), "=r"(r[2]), "=r"(r[3]) : "r"(saddr));
}
__device__ __forceinline__ void cp16(uint32_t dst_sw, const void* src) {
    asm volatile("cp.async.cg.shared.global [%0], [%1], 16;"
                 :: "r"(dst_sw), "l"(src));
}
#define CP_COMMIT() asm volatile("cp.async.commit_group;" ::: "memory")
#define CP_WAIT(N)  asm volatile("cp.async.wait_group %0;" :: "n"(N) : "memory")

// ---------------------------------------------------------------------------
// Kernel 1: DWT (z 0..5) + weight split prologue (z == 6). grid (16,16,7)x256.
// ---------------------------------------------------------------------------
__global__ void __launch_bounds__(256) dwt_kernel(const float* __restrict__ X,
                                                  const float* __restrict__ w1,
                                                  const float* __restrict__ w2)
{
    if (blockIdx.z == 6) {
        int i = (blockIdx.y * 16 + blockIdx.x) * 256 + threadIdx.x;
        if (i < 12288) {                 // W1 words: [hl][n 128][wd 48]
            int hl = i / 6144, rr = i % 6144;
            int n = rr / 48, wd = rr % 48;
            int k0 = 2 * wd;
            float v0 = (k0     < 90) ? w1[n * 90 + k0]     : 0.f;
            float v1 = (k0 + 1 < 90) ? w1[n * 90 + k0 + 1] : 0.f;
            g_W1s[i] = split_word(v0, v1, hl);
        } else if (i < 12288 + 32768) {  // W2 words: [q][hl][n 64][wd 64]
            int j = i - 12288;
            int q  = j >> 13, r1 = j & 8191;
            int hl = r1 >> 12, r2 = r1 & 4095;
            int n  = r2 >> 6,  wd = r2 & 63;
            int ng = q * 64 + n, k0 = 2 * wd;
            float v0 = w2[ng * 128 + k0];
            float v1 = w2[ng * 128 + k0 + 1];
            g_W2s[j] = split_word(v0, v1, hl);
        }
        return;
    }

    const int hw = blockIdx.x * 256 + threadIdx.x;
    const int b  = blockIdx.y;
    const int c0 = blockIdx.z * 15;

    const float* Xp = X + (size_t)b * C_IN * HW + hw;

    const int jstart = 2 * c0 - 2;
    float h1v[32];

    int j = jstart;
    int cA = 2 * j - 2, cB = 2 * j - 1;
    float xm2 = (cA >= 0 && cA < C_IN) ? Xp[(size_t)cA * HW] : 0.f;
    float xm1 = (cB >= 0 && cB < C_IN) ? Xp[(size_t)cB * HW] : 0.f;
#pragma unroll
    for (int t = 0; t < 32; t++) {
        int c2j = 2 * j, c2j1 = 2 * j + 1;
        float x0 = (c2j  >= 0 && c2j  < C_IN) ? Xp[(size_t)c2j  * HW] : 0.f;
        float x1 = (c2j1 >= 0 && c2j1 < C_IN) ? Xp[(size_t)c2j1 * HW] : 0.f;
        float h = 0.f;
        if (j >= 0 && j < 180)
            h = H1_0 * xm2 + H1_1 * xm1 + H1_2 * x0 + H1_3 * x1;
        h1v[t] = h;
        xm2 = x0; xm1 = x1; j++;
    }

    float* Fp = g_F + (size_t)b * C_MID * HW + hw;
#pragma unroll
    for (int u = 0; u < 15; u++) {
        int c2 = c0 + u;
        float a = h1v[2 * u], bb = h1v[2 * u + 1], cc = h1v[2 * u + 2], dd = h1v[2 * u + 3];
        float lo = H0_0 * a + H0_1 * bb + H0_2 * cc + H0_3 * dd;
        float hi = H1_0 * a + H1_1 * bb + H1_2 * cc + H1_3 * dd;
        Fp[(size_t)c2 * HW]        = lo;
        Fp[(size_t)(90 + c2) * HW] = hi;
    }
}

// ---------------------------------------------------------------------------
// Kernel 2: HMMA conv+MLP. 1024 blocks x 256 threads, 64 chunks/block,
// 3 CTAs/SM (71.7KB smem, <=84 regs).
// ---------------------------------------------------------------------------
__global__ void __launch_bounds__(256, 3) mlp_kernel(
    const float* __restrict__ cw, const float* __restrict__ cbp,
    const float* __restrict__ b1, const float* __restrict__ b2,
    float* __restrict__ out)
{
    extern __shared__ uint32_t sw[];
    float* b1s = (float*)(sw + WB1);
    float* b2s = (float*)(sw + WB2);
    const uint32_t swb = (uint32_t)__cvta_generic_to_shared(sw);

    const int tid = threadIdx.x;
    const int n0  = blockIdx.x * 64;
    const int w   = tid >> 5, l = tid & 31;
    const int wm  = w & 1, wn = w >> 1;      // 2 m-warps x 4 n-warps
    const int g   = l >> 2, kp = l & 3;

    const int a_lrow = l & 15;
    const int a_lcol = (l >> 4) * 4;
    const int b_sel  = l >> 3, b_r8 = l & 7;
    const int b_tof  = (b_sel >> 1);
    const int b_col  = (b_sel & 1) * 4;

    // ---- W1 half 0 cp.async (lands during conv) ----
#pragma unroll
    for (int c = 0; c < 6; c++) {
        int i = tid + c * 256;                   // 1536 ops
        int hl = i / 768, rr = i % 768;
        int n = rr / 12, jq = rr % 12;
        uint32_t dst = swb + 4 * (WBUF + (hl ? W1LO : 0) + n * W1_ST + jq * 4);
        cp16(dst, g_W1s + hl * 6144 + n * 48 + jq * 4);
    }
    CP_COMMIT();

    // ---- biases ----
    if (tid < 128) b1s[tid] = b1[tid];
    b2s[tid] = b2[tid];

    // ---- conv: direct-LDG from g_F -> A splits ----
    {
        float c0w[7], c1w[7];
#pragma unroll
        for (int i = 0; i < 7; i++) { c0w[i] = __ldg(cw + i); c1w[i] = __ldg(cw + 7 + i); }
        const float cb = __ldg(cbp);
        const int mloc = tid >> 3, q8 = tid & 7;

#pragma unroll
        for (int fh = 0; fh < 2; fh++) {
            const int mrow = fh * 32 + mloc;
            const float* r0 = g_F + (size_t)(n0 + mrow) * 180;
            const float* r1 = r0 + 90;
            float a0[18], a1[18];
#pragma unroll
            for (int t = 0; t < 18; t++) {
                int idx = q8 * 12 - 3 + t;
                bool ok = (idx >= 0 && idx < 90);
                a0[t] = ok ? __ldg(r0 + idx) : 0.f;
                a1[t] = ok ? __ldg(r1 + idx) : 0.f;
            }
            uint32_t* Ah = sw + WA_HI + mrow * A_ST;
            uint32_t* Al = sw + WA_LO + mrow * A_ST;
#pragma unroll
            for (int pl = 0; pl < 6; pl++) {
                int p = q8 * 6 + pl;
                float v0 = 0.f, v1 = 0.f;
                if (2 * p < 90) {
                    float s0 = cb, s1 = cb;
#pragma unroll
                    for (int kw = 0; kw < 7; kw++) {
                        s0 += c0w[kw] * a0[2 * pl + kw]     + c1w[kw] * a1[2 * pl + kw];
                        s1 += c0w[kw] * a0[2 * pl + 1 + kw] + c1w[kw] * a1[2 * pl + 1 + kw];
                    }
                    v0 = fmaxf(s0, 0.f);
                    v1 = fmaxf(s1, 0.f);
                }
                uint32_t whi, wlo;
                split_pair(v0, v1, whi, wlo);
                Ah[p] = whi;
                Al[p] = wlo;
            }
        }
    }
    CP_WAIT(0);            // W1 half 0 landed
    __syncthreads();       // + A visible

    // ---- GEMM1: [64m x 128n] in 2 N-half passes, K=96 (6 steps) ----
    float acc1[2][4][4];   // [mi][half*2 + t][e]
#pragma unroll
    for (int mi = 0; mi < 2; mi++)
#pragma unroll
        for (int t = 0; t < 4; t++)
#pragma unroll
            for (int e = 0; e < 4; e++) acc1[mi][t][e] = 0.f;

    uint32_t aHi[2], aLo[2];
#pragma unroll
    for (int mi = 0; mi < 2; mi++) {
        int row = (wm * 2 + mi) * 16 + a_lrow;
        aHi[mi] = swb + 4 * (WA_HI + row * A_ST + a_lcol);
        aLo[mi] = swb + 4 * (WA_LO + row * A_ST + a_lcol);
    }
    const int nloc1 = (wn * 2 + b_tof) * 8 + b_r8;   // 0..63 within N-half
    const uint32_t w1Hi = swb + 4 * (WBUF + nloc1 * W1_ST + b_col);
    const uint32_t w1Lo = w1Hi + 4 * W1LO;

#pragma unroll
    for (int half = 0; half < 2; half++) {
#pragma unroll
        for (int s = 0; s < 6; s++) {
            uint32_t ah[2][4], al[2][4], bh[4], bl[4];
            const uint32_t so = s * 32;
            ldsm4(ah[0], aHi[0] + so); ldsm4(ah[1], aHi[1] + so);
            ldsm4(al[0], aLo[0] + so); ldsm4(al[1], aLo[1] + so);
            ldsm4(bh, w1Hi + so);      ldsm4(bl, w1Lo + so);
#pragma unroll
            for (int t = 0; t < 2; t++)
#pragma unroll
                for (int mi = 0; mi < 2; mi++)
                    mma16816(acc1[mi][half * 2 + t], ah[mi], &bh[t * 2]);
#pragma unroll
            for (int t = 0; t < 2; t++)
#pragma unroll
                for (int mi = 0; mi < 2; mi++)
                    mma16816(acc1[mi][half * 2 + t], ah[mi], &bl[t * 2]);
#pragma unroll
            for (int t = 0; t < 2; t++)
#pragma unroll
                for (int mi = 0; mi < 2; mi++)
                    mma16816(acc1[mi][half * 2 + t], al[mi], &bh[t * 2]);
        }
        if (half == 0) {
            __syncthreads();           // W-buffer reads done
#pragma unroll
            for (int c = 0; c < 6; c++) {     // stage W1 half 1
                int i = tid + c * 256;
                int hl = i / 768, rr = i % 768;
                int n = rr / 12, jq = rr % 12;
                uint32_t dst = swb + 4 * (WBUF + (hl ? W1LO : 0) + n * W1_ST + jq * 4);
                cp16(dst, g_W1s + hl * 6144 + (64 + n) * 48 + jq * 4);
            }
            CP_COMMIT();
            CP_WAIT(0);
            __syncthreads();
        }
    }
    __syncthreads();       // A + W-buffer reads done; both dead now

    // stage W2 quarter 0 into W-buffer (overlaps epilogue 1)
#pragma unroll
    for (int c = 0; c < 8; c++) {
        int i = tid + c * 256;               // 2048 ops
        int hl = i >> 10, rr = i & 1023;
        int n = rr >> 4, jq = rr & 15;
        uint32_t dst = swb + 4 * (WBUF + (hl ? QLO : 0) + n * W2_ST + jq * 4);
        cp16(dst, g_W2s + hl * 4096 + n * 64 + jq * 4);
    }
    CP_COMMIT();

    // ---- epilogue 1: relu(+b1) -> H splits (overlays A region) ----
#pragma unroll
    for (int mi = 0; mi < 2; mi++) {
        int r1 = (wm * 2 + mi) * 16 + g, r2 = r1 + 8;
#pragma unroll
        for (int half = 0; half < 2; half++)
#pragma unroll
            for (int t = 0; t < 2; t++) {
                int c = half * 64 + (wn * 2 + t) * 8 + kp * 2;
                float bb0 = b1s[c], bb1 = b1s[c + 1];
                int wc = c >> 1;
                float* ac = acc1[mi][half * 2 + t];
                float v0 = fmaxf(ac[0] + bb0, 0.f);
                float v1 = fmaxf(ac[1] + bb1, 0.f);
                uint32_t whi, wlo;
                split_pair(v0, v1, whi, wlo);
                sw[WH_HI + r1 * H_ST + wc] = whi;
                sw[WH_LO + r1 * H_ST + wc] = wlo;
                float v2 = fmaxf(ac[2] + bb0, 0.f);
                float v3 = fmaxf(ac[3] + bb1, 0.f);
                split_pair(v2, v3, whi, wlo);
                sw[WH_HI + r2 * H_ST + wc] = whi;
                sw[WH_LO + r2 * H_ST + wc] = wlo;
            }
    }
    CP_WAIT(0);            // W2 q0 landed
    __syncthreads();       // H + W2 q0 visible

    // ---- GEMM2: 4 N-quarters of 64, K=128 (8 steps), single W-buffer ----
    uint32_t hHi[2], hLo[2];
#pragma unroll
    for (int mi = 0; mi < 2; mi++) {
        int row = (wm * 2 + mi) * 16 + a_lrow;
        hHi[mi] = swb + 4 * (WH_HI + row * H_ST + a_lcol);
        hLo[mi] = swb + 4 * (WH_LO + row * H_ST + a_lcol);
    }
    const int nloc = (wn * 2 + b_tof) * 8 + b_r8;
    const uint32_t w2Hi = swb + 4 * (WBUF + nloc * W2_ST + b_col);
    const uint32_t w2Lo = w2Hi + 4 * QLO;

#pragma unroll
    for (int q = 0; q < 4; q++) {
        float acc2[2][2][4];
#pragma unroll
        for (int mi = 0; mi < 2; mi++)
#pragma unroll
            for (int t = 0; t < 2; t++)
#pragma unroll
                for (int e = 0; e < 4; e++) acc2[mi][t][e] = 0.f;

#pragma unroll
        for (int s = 0; s < 8; s++) {
            uint32_t ah[2][4], al[2][4], bh[4], bl[4];
            const uint32_t so = s * 32;
            ldsm4(ah[0], hHi[0] + so); ldsm4(ah[1], hHi[1] + so);
            ldsm4(al[0], hLo[0] + so); ldsm4(al[1], hLo[1] + so);
            ldsm4(bh, w2Hi + so);      ldsm4(bl, w2Lo + so);
#pragma unroll
            for (int t = 0; t < 2; t++)
#pragma unroll
                for (int mi = 0; mi < 2; mi++)
                    mma16816(acc2[mi][t], ah[mi], &bh[t * 2]);
#pragma unroll
            for (int t = 0; t < 2; t++)
#pragma unroll
                for (int mi = 0; mi < 2; mi++)
                    mma16816(acc2[mi][t], ah[mi], &bl[t * 2]);
#pragma unroll
            for (int t = 0; t < 2; t++)
#pragma unroll
                for (int mi = 0; mi < 2; mi++)
                    mma16816(acc2[mi][t], al[mi], &bh[t * 2]);
        }

        // epilogue: +b2 -> out
#pragma unroll
        for (int mi = 0; mi < 2; mi++) {
            int r1 = (wm * 2 + mi) * 16 + g, r2 = r1 + 8;
#pragma unroll
            for (int t = 0; t < 2; t++) {
                int c = q * 64 + (wn * 2 + t) * 8 + kp * 2;
                float bb0 = b2s[c], bb1 = b2s[c + 1];
                float2 v01 = make_float2(acc2[mi][t][0] + bb0, acc2[mi][t][1] + bb1);
                float2 v23 = make_float2(acc2[mi][t][2] + bb0, acc2[mi][t][3] + bb1);
                *(float2*)(out + (size_t)(n0 + r1) * 256 + c) = v01;
                *(float2*)(out + (size_t)(n0 + r2) * 256 + c) = v23;
            }
        }

        if (q < 3) {
            __syncthreads();                    // W-buffer reads done
#pragma unroll
            for (int c = 0; c < 8; c++) {       // stage quarter q+1
                int i = tid + c * 256;
                int hl = i >> 10, rr = i & 1023;
                int n = rr >> 4, jq = rr & 15;
                uint32_t dst = swb + 4 * (WBUF + (hl ? QLO : 0) + n * W2_ST + jq * 4);
                cp16(dst, g_W2s + (q + 1) * 8192 + hl * 4096 + n * 64 + jq * 4);
            }
            CP_COMMIT();
            CP_WAIT(0);
            __syncthreads();
        }
    }
}

// ---------------------------------------------------------------------------
extern "C" void kernel_launch(void* const* d_in, const int* in_sizes, int n_in,
                              void* d_out, int out_size)
{
    const float* x      = (const float*)d_in[0];
    const float* conv_w = (const float*)d_in[1];
    const float* conv_b = (const float*)d_in[2];
    const float* w1     = (const float*)d_in[3];
    const float* b1     = (const float*)d_in[4];
    const float* w2     = (const float*)d_in[5];
    const float* b2     = (const float*)d_in[6];
    float* out = (float*)d_out;

    (void)in_sizes; (void)n_in; (void)out_size;

    // Stage 1: double DWT -> g_F, plus weight split prologue in z-slice 6
    dim3 g1(HW / 256, B_DIM, 7);
    dwt_kernel<<<g1, 256>>>(x, w1, w2);

    // Stage 2: conv + HMMA MLP (3 CTAs/SM)
    cudaFuncSetAttribute(mlp_kernel,
                         cudaFuncAttributeMaxDynamicSharedMemorySize, SMEM_BYTES);
    mlp_kernel<<<1024, 256, SMEM_BYTES>>>(conv_w, conv_b, b1, b2, out);
}

// round 17
// speedup vs baseline: 2.0973x; 1.0638x over previous
#include <cuda_runtime.h>
#include <cuda_bf16.h>
#include <cstdint>

// ---------------------------------------------------------------------------
// ToFace_Unet_Dwt_locate — R17: R16 with the conv ld1 off-by-one fixed
// (a1[t] = ld1[t+1], matching ld0). GEMM2 in 2 N-halves (-33% GEMM2 ldsm
// traffic), full W1 resident, vectorized conv. 106.5KB smem, 2 CTAs/SM.
// ---------------------------------------------------------------------------

#define H0_0 0.48296291314469025f
#define H0_1 0.836516303737469f
#define H0_2 0.22414386804185735f
#define H0_3 (-0.12940952255092145f)
#define H1_0 0.12940952255092145f
#define H1_1 (-0.22414386804185735f)
#define H1_2 0.836516303737469f
#define H1_3 (-0.48296291314469025f)

#define B_DIM 16
#define C_IN 360
#define HW 4096
#define C_MID 180

// smem word offsets
#define WB1    0          // b1: 128 f32
#define WB2    128        // b2: 256 f32 (pad to 512)
#define WA_HI  512        // A hi [64][52] (ends 3840)
#define WA_LO  3840       // A lo [64][52] (ends 7168)
#define WH_HI  512        // H hi [64][68] (overlays A post-GEMM1)
#define WH_LO  4864       // H lo [64][68] (ends 9216)
#define WBUF   9216       // W1 full [hl 6656] OR W2 half [hl 8704]
#define W1LO   6656
#define W2LO   8704
#define SMEM_WORDS 26624
#define SMEM_BYTES (SMEM_WORDS * 4)   // 106496

#define A_ST  52
#define W1_ST 52
#define W2_ST 68
#define H_ST  68

__device__ float g_F[(size_t)B_DIM * C_MID * HW + 16];  // +pad for vec tails
__device__ uint32_t g_W1s[12288];                   // [hl][128 n][48 wd]
__device__ uint32_t g_W2s[32768];                   // [half][hl][128 n][64 wd]

// ---- helpers --------------------------------------------------------------
__device__ __forceinline__ uint32_t pack_bf16(__nv_bfloat16 lo, __nv_bfloat16 hi) {
    return ((uint32_t)__bfloat16_as_ushort(hi) << 16) | __bfloat16_as_ushort(lo);
}
__device__ __forceinline__ void split_pair(float v0, float v1,
                                           uint32_t& whi, uint32_t& wlo) {
    __nv_bfloat16 h0 = __float2bfloat16(v0);
    __nv_bfloat16 h1 = __float2bfloat16(v1);
    float r0 = v0 - __bfloat162float(h0);
    float r1 = v1 - __bfloat162float(h1);
    whi = pack_bf16(h0, h1);
    wlo = pack_bf16(__float2bfloat16(r0), __float2bfloat16(r1));
}
__device__ __forceinline__ uint32_t split_word(float v0, float v1, int hl) {
    uint32_t a, b;
    split_pair(v0, v1, a, b);
    return hl ? b : a;
}
__device__ __forceinline__ void mma16816(float* d, const uint32_t* a,
                                         const uint32_t* b) {
    asm volatile(
        "mma.sync.aligned.m16n8k16.row.col.f32.bf16.bf16.f32 "
        "{%0,%1,%2,%3}, {%4,%5,%6,%7}, {%8,%9}, {%0,%1,%2,%3};"
        : "+f"(d[0]), "+f"(d[1]), "+f"(d[2]), "+f"(d[3])
        : "r"(a[0]), "r"(a[1]), "r"(a[2]), "r"(a[3]), "r"(b[0]), "r"(b[1]));
}
__device__ __forceinline__ void ldsm4(uint32_t* r, uint32_t saddr) {
    asm volatile("ldmatrix.sync.aligned.m8n8.x4.shared.b16 {%0,%1,%2,%3}, [%4];"
                 : "=r"(r[0]), "=r"(r[1]), "=r"(r[2]), "=r"(r[3]) : "r"(saddr));
}
__device__ __forceinline__ void cp16(uint32_t dst_sw, const void* src) {
    asm volatile("cp.async.cg.shared.global [%0], [%1], 16;"
                 :: "r"(dst_sw), "l"(src));
}
#define CP_COMMIT() asm volatile("cp.async.commit_group;" ::: "memory")
#define CP_WAIT(N)  asm volatile("cp.async.wait_group %0;" :: "n"(N) : "memory")

// ---------------------------------------------------------------------------
// Kernel 1: DWT (z 0..5) + weight split prologue (z == 6). grid (16,16,7)x256.
// ---------------------------------------------------------------------------
__global__ void __launch_bounds__(256) dwt_kernel(const float* __restrict__ X,
                                                  const float* __restrict__ w1,
                                                  const float* __restrict__ w2)
{
    if (blockIdx.z == 6) {
        int i = (blockIdx.y * 16 + blockIdx.x) * 256 + threadIdx.x;
        if (i < 12288) {                 // W1 words: [hl][n 128][wd 48]
            int hl = i / 6144, rr = i % 6144;
            int n = rr / 48, wd = rr % 48;
            int k0 = 2 * wd;
            float v0 = (k0     < 90) ? w1[n * 90 + k0]     : 0.f;
            float v1 = (k0 + 1 < 90) ? w1[n * 90 + k0 + 1] : 0.f;
            g_W1s[i] = split_word(v0, v1, hl);
        } else if (i < 12288 + 32768) {  // W2 words: [half][hl][n 128][wd 64]
            int j = i - 12288;
            int half = j >> 14;
            int hl = (j >> 13) & 1;
            int n  = (j >> 6) & 127, wd = j & 63;
            int ng = half * 128 + n, k0 = 2 * wd;
            float v0 = w2[ng * 128 + k0];
            float v1 = w2[ng * 128 + k0 + 1];
            g_W2s[j] = split_word(v0, v1, hl);
        }
        return;
    }

    const int hw = blockIdx.x * 256 + threadIdx.x;
    const int b  = blockIdx.y;
    const int c0 = blockIdx.z * 15;

    const float* Xp = X + (size_t)b * C_IN * HW + hw;

    const int jstart = 2 * c0 - 2;
    float h1v[32];

    int j = jstart;
    int cA = 2 * j - 2, cB = 2 * j - 1;
    float xm2 = (cA >= 0 && cA < C_IN) ? Xp[(size_t)cA * HW] : 0.f;
    float xm1 = (cB >= 0 && cB < C_IN) ? Xp[(size_t)cB * HW] : 0.f;
#pragma unroll
    for (int t = 0; t < 32; t++) {
        int c2j = 2 * j, c2j1 = 2 * j + 1;
        float x0 = (c2j  >= 0 && c2j  < C_IN) ? Xp[(size_t)c2j  * HW] : 0.f;
        float x1 = (c2j1 >= 0 && c2j1 < C_IN) ? Xp[(size_t)c2j1 * HW] : 0.f;
        float h = 0.f;
        if (j >= 0 && j < 180)
            h = H1_0 * xm2 + H1_1 * xm1 + H1_2 * x0 + H1_3 * x1;
        h1v[t] = h;
        xm2 = x0; xm1 = x1; j++;
    }

    float* Fp = g_F + (size_t)b * C_MID * HW + hw;
#pragma unroll
    for (int u = 0; u < 15; u++) {
        int c2 = c0 + u;
        float a = h1v[2 * u], bb = h1v[2 * u + 1], cc = h1v[2 * u + 2], dd = h1v[2 * u + 3];
        float lo = H0_0 * a + H0_1 * bb + H0_2 * cc + H0_3 * dd;
        float hi = H1_0 * a + H1_1 * bb + H1_2 * cc + H1_3 * dd;
        Fp[(size_t)c2 * HW]        = lo;
        Fp[(size_t)(90 + c2) * HW] = hi;
    }
}

// ---------------------------------------------------------------------------
// Kernel 2: HMMA conv+MLP. 1024 blocks x 256 threads, 64 chunks/block,
// 2 CTAs/SM. GEMM2 in 2 N-halves.
// ---------------------------------------------------------------------------
__global__ void __launch_bounds__(256, 2) mlp_kernel(
    const float* __restrict__ cw, const float* __restrict__ cbp,
    const float* __restrict__ b1, const float* __restrict__ b2,
    float* __restrict__ out)
{
    extern __shared__ uint32_t sw[];
    float* b1s = (float*)(sw + WB1);
    float* b2s = (float*)(sw + WB2);
    const uint32_t swb = (uint32_t)__cvta_generic_to_shared(sw);

    const int tid = threadIdx.x;
    const int n0  = blockIdx.x * 64;
    const int w   = tid >> 5, l = tid & 31;
    const int wm  = w & 1, wn = w >> 1;      // 2 m-warps x 4 n-warps
    const int g   = l >> 2, kp = l & 3;

    const int a_lrow = l & 15;
    const int a_lcol = (l >> 4) * 4;
    const int b_sel  = l >> 3, b_r8 = l & 7;
    const int b_tof  = (b_sel >> 1);
    const int b_col  = (b_sel & 1) * 4;

    // ---- W1 full cp.async (lands during conv) ----
#pragma unroll
    for (int c = 0; c < 12; c++) {
        int o = tid + c * 256;                   // 3072 ops
        int hl = o / 1536, rr = o % 1536;
        int n = rr / 12, jq = rr % 12;
        uint32_t dst = swb + 4 * (WBUF + hl * W1LO + n * W1_ST + jq * 4);
        cp16(dst, g_W1s + hl * 6144 + n * 48 + jq * 4);
    }
    CP_COMMIT();

    // ---- biases ----
    if (tid < 128) b1s[tid] = b1[tid];
    b2s[tid] = b2[tid];

    // ---- conv: vectorized LDG from g_F -> A splits ----
    {
        float c0w[7], c1w[7];
#pragma unroll
        for (int i = 0; i < 7; i++) { c0w[i] = __ldg(cw + i); c1w[i] = __ldg(cw + 7 + i); }
        const float cb = __ldg(cbp);
        const int mloc = tid >> 3, q8 = tid & 7;
        const int w0 = q8 * 12 - 3;              // first conv-window element

#pragma unroll
        for (int fh = 0; fh < 2; fh++) {
            const int mrow = fh * 32 + mloc;
            const float* r0 = g_F + (size_t)(n0 + mrow) * 180;
            float ld0[20], ld1[20];
            // r0: 5 guarded float4 (16B-aligned; clamp f<0 to 0)
            //   ld0[i] = r0[12*q8 - 4 + i]
#pragma unroll
            for (int t4 = 0; t4 < 5; t4++) {
                int f = 3 * q8 - 1 + t4;
                int fc = f < 0 ? 0 : f;
                float4 v = *(const float4*)(r0 + 4 * fc);
                ld0[4 * t4] = v.x; ld0[4 * t4 + 1] = v.y;
                ld0[4 * t4 + 2] = v.z; ld0[4 * t4 + 3] = v.w;
            }
            // r1 (= r0+90, 8B-aligned): 10 guarded float2
            //   ld1[i] = r1[12*q8 - 4 + i]  (same origin as ld0)
#pragma unroll
            for (int t2 = 0; t2 < 10; t2++) {
                int f = 6 * q8 - 2 + t2;
                int fc = f < 0 ? 0 : f;
                float2 v = *(const float2*)(r0 + 90 + 2 * fc);
                ld1[2 * t2] = v.x; ld1[2 * t2 + 1] = v.y;
            }
            float a0[18], a1[18];
#pragma unroll
            for (int t = 0; t < 18; t++) {
                int idx = w0 + t;
                bool ok = (idx >= 0 && idx < 90);
                a0[t] = ok ? ld0[t + 1] : 0.f;
                a1[t] = ok ? ld1[t + 1] : 0.f;   // FIXED: was ld1[t+2]
            }
            uint32_t* Ah = sw + WA_HI + mrow * A_ST;
            uint32_t* Al = sw + WA_LO + mrow * A_ST;
#pragma unroll
            for (int pl = 0; pl < 6; pl++) {
                int p = q8 * 6 + pl;
                float v0 = 0.f, v1 = 0.f;
                if (2 * p < 90) {
                    float s0 = cb, s1 = cb;
#pragma unroll
                    for (int kw = 0; kw < 7; kw++) {
                        s0 += c0w[kw] * a0[2 * pl + kw]     + c1w[kw] * a1[2 * pl + kw];
                        s1 += c0w[kw] * a0[2 * pl + 1 + kw] + c1w[kw] * a1[2 * pl + 1 + kw];
                    }
                    v0 = fmaxf(s0, 0.f);
                    v1 = fmaxf(s1, 0.f);
                }
                uint32_t whi, wlo;
                split_pair(v0, v1, whi, wlo);
                Ah[p] = whi;
                Al[p] = wlo;
            }
        }
    }
    CP_WAIT(0);            // W1 landed
    __syncthreads();       // + A visible

    // ---- GEMM1: [64m x 128n], K=96 (6 steps), 3-term, full W1 ----
    float acc1[2][4][4];
#pragma unroll
    for (int mi = 0; mi < 2; mi++)
#pragma unroll
        for (int t = 0; t < 4; t++)
#pragma unroll
            for (int e = 0; e < 4; e++) acc1[mi][t][e] = 0.f;

    uint32_t aHi[2], aLo[2];
#pragma unroll
    for (int mi = 0; mi < 2; mi++) {
        int row = (wm * 2 + mi) * 16 + a_lrow;
        aHi[mi] = swb + 4 * (WA_HI + row * A_ST + a_lcol);
        aLo[mi] = swb + 4 * (WA_LO + row * A_ST + a_lcol);
    }
    {
        uint32_t bHi[2], bLo[2];
#pragma unroll
        for (int tp = 0; tp < 2; tp++) {
            int n = (wn * 4 + 2 * tp + b_tof) * 8 + b_r8;
            bHi[tp] = swb + 4 * (WBUF + n * W1_ST + b_col);
            bLo[tp] = bHi[tp] + 4 * W1LO;
        }
#pragma unroll
        for (int s = 0; s < 6; s++) {
            uint32_t ah[2][4], al[2][4], bh[2][4], bl[2][4];
            const uint32_t so = s * 32;
            ldsm4(ah[0], aHi[0] + so); ldsm4(ah[1], aHi[1] + so);
            ldsm4(al[0], aLo[0] + so); ldsm4(al[1], aLo[1] + so);
            ldsm4(bh[0], bHi[0] + so); ldsm4(bh[1], bHi[1] + so);
            ldsm4(bl[0], bLo[0] + so); ldsm4(bl[1], bLo[1] + so);
#pragma unroll
            for (int t = 0; t < 4; t++)
#pragma unroll
                for (int mi = 0; mi < 2; mi++)
                    mma16816(acc1[mi][t], ah[mi], &bh[t >> 1][(t & 1) * 2]);
#pragma unroll
            for (int t = 0; t < 4; t++)
#pragma unroll
                for (int mi = 0; mi < 2; mi++)
                    mma16816(acc1[mi][t], ah[mi], &bl[t >> 1][(t & 1) * 2]);
#pragma unroll
            for (int t = 0; t < 4; t++)
#pragma unroll
                for (int mi = 0; mi < 2; mi++)
                    mma16816(acc1[mi][t], al[mi], &bh[t >> 1][(t & 1) * 2]);
        }
    }
    __syncthreads();       // A + W1 reads done; regions reusable

    // ---- stage W2 half 0 (overlaps epilogue 1) ----
#pragma unroll
    for (int c = 0; c < 16; c++) {
        int o = tid + c * 256;               // 4096 ops
        int hl = o >> 11, rr = o & 2047;
        int n = rr >> 4, jq = rr & 15;
        uint32_t dst = swb + 4 * (WBUF + hl * W2LO + n * W2_ST + jq * 4);
        cp16(dst, g_W2s + hl * 8192 + n * 64 + jq * 4);
    }
    CP_COMMIT();

    // ---- epilogue 1: relu(+b1) -> H splits (overlays A region) ----
#pragma unroll
    for (int mi = 0; mi < 2; mi++) {
        int r1 = (wm * 2 + mi) * 16 + g, r2 = r1 + 8;
#pragma unroll
        for (int t = 0; t < 4; t++) {
            int tile = wn * 4 + t;
            int c = tile * 8 + kp * 2;
            float bb0 = b1s[c], bb1 = b1s[c + 1];
            int wc = tile * 4 + kp;
            float v0 = fmaxf(acc1[mi][t][0] + bb0, 0.f);
            float v1 = fmaxf(acc1[mi][t][1] + bb1, 0.f);
            uint32_t whi, wlo;
            split_pair(v0, v1, whi, wlo);
            sw[WH_HI + r1 * H_ST + wc] = whi;
            sw[WH_LO + r1 * H_ST + wc] = wlo;
            float v2 = fmaxf(acc1[mi][t][2] + bb0, 0.f);
            float v3 = fmaxf(acc1[mi][t][3] + bb1, 0.f);
            split_pair(v2, v3, whi, wlo);
            sw[WH_HI + r2 * H_ST + wc] = whi;
            sw[WH_LO + r2 * H_ST + wc] = wlo;
        }
    }
    CP_WAIT(0);            // W2 half0 landed
    __syncthreads();       // H + W2 half0 visible

    // ---- GEMM2: 2 N-halves of 128, K=128 (8 steps) ----
    uint32_t hHi[2], hLo[2];
#pragma unroll
    for (int mi = 0; mi < 2; mi++) {
        int row = (wm * 2 + mi) * 16 + a_lrow;
        hHi[mi] = swb + 4 * (WH_HI + row * H_ST + a_lcol);
        hLo[mi] = swb + 4 * (WH_LO + row * H_ST + a_lcol);
    }
    uint32_t w2Hi[2], w2Lo[2];
#pragma unroll
    for (int tp = 0; tp < 2; tp++) {
        int n = (wn * 4 + 2 * tp + b_tof) * 8 + b_r8;
        w2Hi[tp] = swb + 4 * (WBUF + n * W2_ST + b_col);
        w2Lo[tp] = w2Hi[tp] + 4 * W2LO;
    }

#pragma unroll
    for (int h = 0; h < 2; h++) {
        float acc2[2][4][4];
#pragma unroll
        for (int mi = 0; mi < 2; mi++)
#pragma unroll
            for (int t = 0; t < 4; t++)
#pragma unroll
                for (int e = 0; e < 4; e++) acc2[mi][t][e] = 0.f;

#pragma unroll
        for (int s = 0; s < 8; s++) {
            uint32_t ah[2][4], al[2][4], bh[2][4], bl[2][4];
            const uint32_t so = s * 32;
            ldsm4(ah[0], hHi[0] + so);  ldsm4(ah[1], hHi[1] + so);
            ldsm4(al[0], hLo[0] + so);  ldsm4(al[1], hLo[1] + so);
            ldsm4(bh[0], w2Hi[0] + so); ldsm4(bh[1], w2Hi[1] + so);
            ldsm4(bl[0], w2Lo[0] + so); ldsm4(bl[1], w2Lo[1] + so);
#pragma unroll
            for (int t = 0; t < 4; t++)
#pragma unroll
                for (int mi = 0; mi < 2; mi++)
                    mma16816(acc2[mi][t], ah[mi], &bh[t >> 1][(t & 1) * 2]);
#pragma unroll
            for (int t = 0; t < 4; t++)
#pragma unroll
                for (int mi = 0; mi < 2; mi++)
                    mma16816(acc2[mi][t], ah[mi], &bl[t >> 1][(t & 1) * 2]);
#pragma unroll
            for (int t = 0; t < 4; t++)
#pragma unroll
                for (int mi = 0; mi < 2; mi++)
                    mma16816(acc2[mi][t], al[mi], &bh[t >> 1][(t & 1) * 2]);
        }

        // epilogue: +b2 -> out
#pragma unroll
        for (int mi = 0; mi < 2; mi++) {
            int r1 = (wm * 2 + mi) * 16 + g, r2 = r1 + 8;
#pragma unroll
            for (int t = 0; t < 4; t++) {
                int c = h * 128 + (wn * 4 + t) * 8 + kp * 2;
                float bb0 = b2s[c], bb1 = b2s[c + 1];
                float2 v01 = make_float2(acc2[mi][t][0] + bb0, acc2[mi][t][1] + bb1);
                float2 v23 = make_float2(acc2[mi][t][2] + bb0, acc2[mi][t][3] + bb1);
                *(float2*)(out + (size_t)(n0 + r1) * 256 + c) = v01;
                *(float2*)(out + (size_t)(n0 + r2) * 256 + c) = v23;
            }
        }

        if (h == 0) {
            __syncthreads();                    // W-buffer reads done
#pragma unroll
            for (int c = 0; c < 16; c++) {      // stage W2 half 1
                int o = tid + c * 256;
                int hl = o >> 11, rr = o & 2047;
                int n = rr >> 4, jq = rr & 15;
                uint32_t dst = swb + 4 * (WBUF + hl * W2LO + n * W2_ST + jq * 4);
                cp16(dst, g_W2s + 16384 + hl * 8192 + n * 64 + jq * 4);
            }
            CP_COMMIT();
            CP_WAIT(0);
            __syncthreads();
        }
    }
}

// ---------------------------------------------------------------------------
extern "C" void kernel_launch(void* const* d_in, const int* in_sizes, int n_in,
                              void* d_out, int out_size)
{
    const float* x      = (const float*)d_in[0];
    const float* conv_w = (const float*)d_in[1];
    const float* conv_b = (const float*)d_in[2];
    const float* w1     = (const float*)d_in[3];
    const float* b1     = (const float*)d_in[4];
    const float* w2     = (const float*)d_in[5];
    const float* b2     = (const float*)d_in[6];
    float* out = (float*)d_out;

    (void)in_sizes; (void)n_in; (void)out_size;

    // Stage 1: double DWT -> g_F, plus weight split prologue in z-slice 6
    dim3 g1(HW / 256, B_DIM, 7);
    dwt_kernel<<<g1, 256>>>(x, w1, w2);

    // Stage 2: conv + HMMA MLP (2 CTAs/SM)
    cudaFuncSetAttribute(mlp_kernel,
                         cudaFuncAttributeMaxDynamicSharedMemorySize, SMEM_BYTES);
    mlp_kernel<<<1024, 256, SMEM_BYTES>>>(conv_w, conv_b, b1, b2, out);
}